// round 1
// baseline (speedup 1.0000x reference)
#include <cuda_runtime.h>

// Shapes (fixed by the problem)
#define BATCH 1024
#define ISZ   1024
#define NH    8
#define HI    8192      // NH * ISZ
#define MT    8
#define KSZ   8
#define FEAT  65536     // HI * KSZ
#define F4    16384     // FEAT / 4

// -------- device scratch (no allocations allowed) --------
__device__ float4 g_A[8 * F4];       // monomial coeffs, layout [n][f/4], f = hi*8 + k
__device__ float  g_Asum[8 * HI];    // [n][hi]  : coeffs of sum_k y_k
__device__ float  g_Q[15 * HI];      // [p][hi]  : coeffs of sum_k y_k^2 (degree 14)
__device__ float  g_S[2 * BATCH];    // per-row sum / sumsq accumulators
__device__ float  g_mu[BATCH];
__device__ float  g_rstd[BATCH];

// ============================================================
// Pass 0: fold kernel * poly * Chebyshev-monomial into A, Asum, Q.
// One thread per (h,i). Also zeroes g_S for this replay.
// ============================================================
__global__ __launch_bounds__(256) void prep_kernel(
    const float* __restrict__ poly,   // [H, I, M]  (used as poly[h,i,k], K==M)
    const float* __restrict__ kern)   // [H, I, M, K]
{
    int hi = blockIdx.x * blockDim.x + threadIdx.x;
    if (hi < 2 * BATCH) g_S[hi] = 0.0f;
    if (hi >= HI) return;

    // Chebyshev T_m monomial coefficients C[m][n] (coeff of x^n in T_m)
    const float C[8][8] = {
        {  1,  0,  0,  0,   0,    0,  0,  0},
        {  0,  1,  0,  0,   0,    0,  0,  0},
        { -1,  0,  2,  0,   0,    0,  0,  0},
        {  0, -3,  0,  4,   0,    0,  0,  0},
        {  1,  0, -8,  0,   8,    0,  0,  0},
        {  0,  5,  0,-20,   0,   16,  0,  0},
        { -1,  0, 18,  0, -48,    0, 32,  0},
        {  0, -7,  0, 56,   0, -112,  0, 64}};

    float p[8];
    float W[8][8];
#pragma unroll
    for (int k = 0; k < 8; k++) p[k] = poly[hi * 8 + k];
#pragma unroll
    for (int m = 0; m < 8; m++)
#pragma unroll
        for (int k = 0; k < 8; k++)
            W[m][k] = kern[hi * 64 + m * 8 + k];

    // a[k][n] = p[k] * sum_m W[m][k] * C[m][n]
    float a[8][8];
#pragma unroll
    for (int k = 0; k < 8; k++) {
#pragma unroll
        for (int n = 0; n < 8; n++) {
            float s = 0.0f;
#pragma unroll
            for (int m = 0; m < 8; m++) s = fmaf(W[m][k], C[m][n], s);
            a[k][n] = s * p[k];
        }
    }

    // Write A in [n][f] layout (f = hi*8 + k) for coalesced pass-2 reads.
    float* Af = reinterpret_cast<float*>(g_A);
#pragma unroll
    for (int n = 0; n < 8; n++)
#pragma unroll
        for (int k = 0; k < 8; k++)
            Af[n * FEAT + hi * 8 + k] = a[k][n];

    // Asum[n] = sum_k a[k][n]
#pragma unroll
    for (int n = 0; n < 8; n++) {
        float s = 0.0f;
#pragma unroll
        for (int k = 0; k < 8; k++) s += a[k][n];
        g_Asum[n * HI + hi] = s;
    }

    // Q[p] = sum_k sum_{n1+n2=p} a[k][n1] * a[k][n2]
    float q[15];
#pragma unroll
    for (int pp = 0; pp < 15; pp++) q[pp] = 0.0f;
#pragma unroll
    for (int k = 0; k < 8; k++)
#pragma unroll
        for (int n1 = 0; n1 < 8; n1++)
#pragma unroll
            for (int n2 = 0; n2 < 8; n2++)
                q[n1 + n2] = fmaf(a[k][n1], a[k][n2], q[n1 + n2]);
#pragma unroll
    for (int pp = 0; pp < 15; pp++) g_Q[pp * HI + hi] = q[pp];
}

// ============================================================
// Pass 1: per-row sum and sumsq via degree-7 / degree-14 Horner.
// grid = (32 hi-blocks, 16 b-chunks), 256 threads. Thread owns one hi,
// loops 64 batch rows; warp-reduce then float atomicAdd into g_S.
// ============================================================
__global__ __launch_bounds__(256) void stats_kernel(
    const float* __restrict__ x,      // [B, I]
    const float* __restrict__ scale)  // [H, I] -> flat index hi
{
    int hi = blockIdx.x * 256 + threadIdx.x;
    int i  = hi & (ISZ - 1);

    float as[8];
#pragma unroll
    for (int n = 0; n < 8; n++) as[n] = g_Asum[n * HI + hi];
    float q[15];
#pragma unroll
    for (int pp = 0; pp < 15; pp++) q[pp] = g_Q[pp * HI + hi];
    float sc = scale[hi];

    int b0 = blockIdx.y * 64;
#pragma unroll 2
    for (int b = b0; b < b0 + 64; b++) {
        float xv = __ldg(&x[b * ISZ + i]) * sc;

        float s1 = as[7];
#pragma unroll
        for (int n = 6; n >= 0; n--) s1 = fmaf(s1, xv, as[n]);

        float s2 = q[14];
#pragma unroll
        for (int pp = 13; pp >= 0; pp--) s2 = fmaf(s2, xv, q[pp]);

#pragma unroll
        for (int off = 16; off > 0; off >>= 1) {
            s1 += __shfl_xor_sync(0xFFFFFFFFu, s1, off);
            s2 += __shfl_xor_sync(0xFFFFFFFFu, s2, off);
        }
        if ((threadIdx.x & 31) == 0) {
            atomicAdd(&g_S[b], s1);
            atomicAdd(&g_S[BATCH + b], s2);
        }
    }
}

// ============================================================
// Pass 1b: mu / rstd per row.
// ============================================================
__global__ void finalize_kernel()
{
    int b = blockIdx.x * blockDim.x + threadIdx.x;
    if (b >= BATCH) return;
    const float inv = 1.0f / (float)FEAT;
    float mu  = g_S[b] * inv;
    float var = g_S[BATCH + b] * inv - mu * mu;
    g_mu[b]   = mu;
    g_rstd[b] = rsqrtf(var + 1e-5f);
}

// ============================================================
// Pass 2: recompute y via Horner, normalize, write output.
// Thread owns one float4 feature group (4 consecutive k), loops 64 rows.
// grid = (64 f-blocks, 16 b-chunks), 256 threads.
// ============================================================
__global__ __launch_bounds__(256) void emit_kernel(
    const float* __restrict__ x,
    const float* __restrict__ scale,
    const float* __restrict__ gamma,
    const float* __restrict__ beta,
    float* __restrict__ out)
{
    int f4 = blockIdx.x * 256 + threadIdx.x;   // 0..16383
    int hi = f4 >> 1;
    int i  = hi & (ISZ - 1);

    float4 c[8];
#pragma unroll
    for (int n = 0; n < 8; n++) c[n] = g_A[n * F4 + f4];

    float  sc = scale[hi];
    float4 g  = reinterpret_cast<const float4*>(gamma)[f4];
    float4 be = reinterpret_cast<const float4*>(beta)[f4];

    float4* out4 = reinterpret_cast<float4*>(out);
    int b0 = blockIdx.y * 64;
#pragma unroll 2
    for (int b = b0; b < b0 + 64; b++) {
        float xv = __ldg(&x[b * ISZ + i]) * sc;
        float mu = g_mu[b];
        float rs = g_rstd[b];

        float y0 = c[7].x, y1 = c[7].y, y2 = c[7].z, y3 = c[7].w;
#pragma unroll
        for (int n = 6; n >= 0; n--) {
            y0 = fmaf(y0, xv, c[n].x);
            y1 = fmaf(y1, xv, c[n].y);
            y2 = fmaf(y2, xv, c[n].z);
            y3 = fmaf(y3, xv, c[n].w);
        }

        float4 o;
        o.x = fmaf((y0 - mu) * rs, g.x, be.x);
        o.y = fmaf((y1 - mu) * rs, g.y, be.y);
        o.z = fmaf((y2 - mu) * rs, g.z, be.z);
        o.w = fmaf((y3 - mu) * rs, g.w, be.w);
        out4[b * F4 + f4] = o;
    }
}

// ============================================================
extern "C" void kernel_launch(void* const* d_in, const int* in_sizes, int n_in,
                              void* d_out, int out_size)
{
    const float* x     = (const float*)d_in[0];  // [1024, 1024]
    const float* scale = (const float*)d_in[1];  // [8, 1024]
    const float* poly  = (const float*)d_in[2];  // [8, 1024, 8]
    const float* kern  = (const float*)d_in[3];  // [8, 1024, 8, 8]
    const float* gamma = (const float*)d_in[4];  // [65536]
    const float* beta  = (const float*)d_in[5];  // [65536]
    float* out = (float*)d_out;                  // [1024, 65536]

    prep_kernel<<<32, 256>>>(poly, kern);
    stats_kernel<<<dim3(32, 16), 256>>>(x, scale);
    finalize_kernel<<<4, 256>>>();
    emit_kernel<<<dim3(64, 16), 256>>>(x, scale, gamma, beta, out);
}

// round 2
// speedup vs baseline: 1.6808x; 1.6808x over previous
#include <cuda_runtime.h>

// Shapes (fixed by the problem)
#define BATCH 1024
#define ISZ   1024
#define NH    8
#define HI    8192      // NH * ISZ
#define FEAT  65536     // HI * 8
#define F4    16384     // FEAT / 4

// -------- device scratch (no allocations allowed) --------
__device__ float4 g_A[8 * F4];       // monomial coeffs, layout [n][f/4], f = hi*8 + k
__device__ float  g_Asum[8 * HI];    // [n][hi]  : coeffs of sum_k y_k
__device__ float  g_Q[15 * HI];      // [p][hi]  : coeffs of sum_k y_k^2 (degree 14)
__device__ float  g_S[2 * BATCH];    // per-row sum / sumsq accumulators
__device__ float  g_mu[BATCH];
__device__ float  g_rstd[BATCH];

// ============================================================
// Pass 0: fold kernel * poly * Chebyshev-monomial into A, Asum, Q.
// One thread per (h,i). Also zeroes g_S for this replay.
// ============================================================
__global__ __launch_bounds__(256) void prep_kernel(
    const float* __restrict__ poly,   // [H, I, M]
    const float* __restrict__ kern)   // [H, I, M, K]
{
    int hi = blockIdx.x * blockDim.x + threadIdx.x;
    if (hi < 2 * BATCH) g_S[hi] = 0.0f;
    if (hi >= HI) return;

    // Chebyshev T_m monomial coefficients C[m][n]
    const float C[8][8] = {
        {  1,  0,  0,  0,   0,    0,  0,  0},
        {  0,  1,  0,  0,   0,    0,  0,  0},
        { -1,  0,  2,  0,   0,    0,  0,  0},
        {  0, -3,  0,  4,   0,    0,  0,  0},
        {  1,  0, -8,  0,   8,    0,  0,  0},
        {  0,  5,  0,-20,   0,   16,  0,  0},
        { -1,  0, 18,  0, -48,    0, 32,  0},
        {  0, -7,  0, 56,   0, -112,  0, 64}};

    float p[8];
    float W[8][8];
#pragma unroll
    for (int k = 0; k < 8; k++) p[k] = poly[hi * 8 + k];
#pragma unroll
    for (int m = 0; m < 8; m++)
#pragma unroll
        for (int k = 0; k < 8; k++)
            W[m][k] = kern[hi * 64 + m * 8 + k];

    float a[8][8];
#pragma unroll
    for (int k = 0; k < 8; k++) {
#pragma unroll
        for (int n = 0; n < 8; n++) {
            float s = 0.0f;
#pragma unroll
            for (int m = 0; m < 8; m++) s = fmaf(W[m][k], C[m][n], s);
            a[k][n] = s * p[k];
        }
    }

    float* Af = reinterpret_cast<float*>(g_A);
#pragma unroll
    for (int n = 0; n < 8; n++)
#pragma unroll
        for (int k = 0; k < 8; k++)
            Af[n * FEAT + hi * 8 + k] = a[k][n];

#pragma unroll
    for (int n = 0; n < 8; n++) {
        float s = 0.0f;
#pragma unroll
        for (int k = 0; k < 8; k++) s += a[k][n];
        g_Asum[n * HI + hi] = s;
    }

    float q[15];
#pragma unroll
    for (int pp = 0; pp < 15; pp++) q[pp] = 0.0f;
#pragma unroll
    for (int k = 0; k < 8; k++)
#pragma unroll
        for (int n1 = 0; n1 < 8; n1++)
#pragma unroll
            for (int n2 = 0; n2 < 8; n2++)
                q[n1 + n2] = fmaf(a[k][n1], a[k][n2], q[n1 + n2]);
#pragma unroll
    for (int pp = 0; pp < 15; pp++) g_Q[pp * HI + hi] = q[pp];
}

// ============================================================
// Pass 1: per-row sum/sumsq. Thread owns one hi; 8-b register tiles;
// one smem block-reduction per tile (8x fewer shuffles than per-b).
// grid = (32 hi-blocks, 16 b-chunks), 256 threads.
// ============================================================
__global__ __launch_bounds__(256) void stats_kernel(
    const float* __restrict__ x,      // [B, I]
    const float* __restrict__ scale)  // [H, I] flat -> hi
{
    __shared__ float red[16 * 256];

    int hi = blockIdx.x * 256 + threadIdx.x;
    int i  = hi & (ISZ - 1);

    float as[8];
#pragma unroll
    for (int n = 0; n < 8; n++) as[n] = g_Asum[n * HI + hi];
    float q[15];
#pragma unroll
    for (int pp = 0; pp < 15; pp++) q[pp] = g_Q[pp * HI + hi];
    float sc = scale[hi];

    int b0   = blockIdx.y * 64;
    int w    = threadIdx.x >> 5;
    int lane = threadIdx.x & 31;

    for (int tile = 0; tile < 8; tile++) {
        int bt = b0 + tile * 8;
#pragma unroll
        for (int bb = 0; bb < 8; bb++) {
            float xv = __ldg(&x[(bt + bb) * ISZ + i]) * sc;

            float s1 = as[7];
#pragma unroll
            for (int n = 6; n >= 0; n--) s1 = fmaf(s1, xv, as[n]);
            float s2 = q[14];
#pragma unroll
            for (int pp = 13; pp >= 0; pp--) s2 = fmaf(s2, xv, q[pp]);

            red[(2 * bb)     * 256 + threadIdx.x] = s1;
            red[(2 * bb + 1) * 256 + threadIdx.x] = s2;
        }
        __syncthreads();
#pragma unroll
        for (int s = w; s < 16; s += 8) {
            float v = 0.0f;
#pragma unroll
            for (int j = 0; j < 8; j++) v += red[s * 256 + lane + j * 32];
#pragma unroll
            for (int off = 16; off > 0; off >>= 1)
                v += __shfl_xor_sync(0xFFFFFFFFu, v, off);
            if (lane == 0)
                atomicAdd(&g_S[(s & 1) * BATCH + bt + (s >> 1)], v);
        }
        __syncthreads();
    }
}

// ============================================================
// Pass 1b: mu / rstd per row.
// ============================================================
__global__ void finalize_kernel()
{
    int b = blockIdx.x * blockDim.x + threadIdx.x;
    if (b >= BATCH) return;
    const float inv = 1.0f / (float)FEAT;
    float mu  = g_S[b] * inv;
    float var = g_S[BATCH + b] * inv - mu * mu;
    g_mu[b]   = mu;
    g_rstd[b] = rsqrtf(var + 1e-5f);
}

// ============================================================
// Pass 2: recompute y via Horner, normalize, stream-write output.
// Block: 256 threads = 256 f4 groups = 128 hi (128 consecutive i, one head).
// Stage x tile [64 b][128 i] + mu/rstd in smem once; hot loop has no gmem loads.
// grid = (64 f-blocks, 16 b-chunks), 256 threads.
// ============================================================
__global__ __launch_bounds__(256) void emit_kernel(
    const float* __restrict__ x,
    const float* __restrict__ scale,
    const float* __restrict__ gamma,
    const float* __restrict__ beta,
    float* __restrict__ out)
{
    __shared__ float xs[64 * 128];
    __shared__ float smu[64];
    __shared__ float srs[64];

    int f4 = blockIdx.x * 256 + threadIdx.x;   // 0..16383
    int hi = f4 >> 1;
    int i0 = (blockIdx.x * 128) & (ISZ - 1);   // tile's base i
    int b0 = blockIdx.y * 64;

    // Cooperative stage of x tile: 64 rows x 128 floats = 2048 float4
    {
        float4*       xs4 = reinterpret_cast<float4*>(xs);
        for (int t = threadIdx.x; t < 2048; t += 256) {
            int bb = t >> 5;
            int c4 = t & 31;
            xs4[t] = __ldg(reinterpret_cast<const float4*>(
                               x + (b0 + bb) * ISZ + i0) + c4);
        }
    }
    if (threadIdx.x < 64)       smu[threadIdx.x]      = g_mu[b0 + threadIdx.x];
    else if (threadIdx.x < 128) srs[threadIdx.x - 64] = g_rstd[b0 + threadIdx.x - 64];

    float4 c[8];
#pragma unroll
    for (int n = 0; n < 8; n++) c[n] = g_A[n * F4 + f4];

    float  sc = scale[hi];
    float4 g  = reinterpret_cast<const float4*>(gamma)[f4];
    float4 be = reinterpret_cast<const float4*>(beta)[f4];

    __syncthreads();

    int il = threadIdx.x >> 1;                 // local i within tile
    float4* out4 = reinterpret_cast<float4*>(out);

#pragma unroll 4
    for (int bb = 0; bb < 64; bb++) {
        float xv = xs[bb * 128 + il] * sc;
        float mu = smu[bb];
        float rs = srs[bb];

        float y0 = c[7].x, y1 = c[7].y, y2 = c[7].z, y3 = c[7].w;
#pragma unroll
        for (int n = 6; n >= 0; n--) {
            y0 = fmaf(y0, xv, c[n].x);
            y1 = fmaf(y1, xv, c[n].y);
            y2 = fmaf(y2, xv, c[n].z);
            y3 = fmaf(y3, xv, c[n].w);
        }

        float4 o;
        o.x = fmaf((y0 - mu) * rs, g.x, be.x);
        o.y = fmaf((y1 - mu) * rs, g.y, be.y);
        o.z = fmaf((y2 - mu) * rs, g.z, be.z);
        o.w = fmaf((y3 - mu) * rs, g.w, be.w);
        __stcs(&out4[(size_t)(b0 + bb) * F4 + f4], o);
    }
}

// ============================================================
extern "C" void kernel_launch(void* const* d_in, const int* in_sizes, int n_in,
                              void* d_out, int out_size)
{
    const float* x     = (const float*)d_in[0];  // [1024, 1024]
    const float* scale = (const float*)d_in[1];  // [8, 1024]
    const float* poly  = (const float*)d_in[2];  // [8, 1024, 8]
    const float* kern  = (const float*)d_in[3];  // [8, 1024, 8, 8]
    const float* gamma = (const float*)d_in[4];  // [65536]
    const float* beta  = (const float*)d_in[5];  // [65536]
    float* out = (float*)d_out;                  // [1024, 65536]

    prep_kernel<<<32, 256>>>(poly, kern);
    stats_kernel<<<dim3(32, 16), 256>>>(x, scale);
    finalize_kernel<<<4, 256>>>();
    emit_kernel<<<dim3(64, 16), 256>>>(x, scale, gamma, beta, out);
}

// round 3
// speedup vs baseline: 2.0101x; 1.1959x over previous
#include <cuda_runtime.h>

// Shapes (fixed by the problem)
#define BATCH 1024
#define ISZ   1024
#define NH    8
#define HI    8192      // NH * ISZ
#define FEAT  65536     // HI * 8
#define F4    16384     // FEAT / 4

// -------- device scratch (no allocations allowed) --------
__device__ float4 g_A[8 * F4];       // monomial coeffs, layout [n][f/4], f = hi*8 + k
__device__ float  g_Asum[8 * HI];    // [n][hi]  : coeffs of sum_k y_k (unscaled)
__device__ float  g_Q[15 * HI];      // [p][hi]  : coeffs of sum_k y_k^2 (unscaled)
__device__ float  g_B1[8 * ISZ];     // [n][i]   : head-folded, scale-folded
__device__ float  g_B2[15 * ISZ];    // [p][i]
__device__ float  g_S[2 * BATCH];    // per-row sum / sumsq accumulators
__device__ float  g_mu[BATCH];
__device__ float  g_rstd[BATCH];

// ============================================================
// Pass 0: fold kernel * poly * Chebyshev-monomial into A, Asum, Q.
// One thread per (h,i). Also zeroes g_S for this replay.
// ============================================================
__global__ __launch_bounds__(256) void prep_kernel(
    const float* __restrict__ poly,   // [H, I, M]
    const float* __restrict__ kern)   // [H, I, M, K]
{
    int hi = blockIdx.x * blockDim.x + threadIdx.x;
    if (hi < 2 * BATCH) g_S[hi] = 0.0f;
    if (hi >= HI) return;

    // Chebyshev T_m monomial coefficients C[m][n]
    const float C[8][8] = {
        {  1,  0,  0,  0,   0,    0,  0,  0},
        {  0,  1,  0,  0,   0,    0,  0,  0},
        { -1,  0,  2,  0,   0,    0,  0,  0},
        {  0, -3,  0,  4,   0,    0,  0,  0},
        {  1,  0, -8,  0,   8,    0,  0,  0},
        {  0,  5,  0,-20,   0,   16,  0,  0},
        { -1,  0, 18,  0, -48,    0, 32,  0},
        {  0, -7,  0, 56,   0, -112,  0, 64}};

    float p[8];
    float W[8][8];
    {
        const float4* p4 = reinterpret_cast<const float4*>(poly + hi * 8);
        float4 pa = __ldg(p4), pb = __ldg(p4 + 1);
        p[0]=pa.x; p[1]=pa.y; p[2]=pa.z; p[3]=pa.w;
        p[4]=pb.x; p[5]=pb.y; p[6]=pb.z; p[7]=pb.w;
        const float4* k4 = reinterpret_cast<const float4*>(kern + hi * 64);
#pragma unroll
        for (int m = 0; m < 8; m++) {
            float4 wa = __ldg(k4 + 2 * m), wb = __ldg(k4 + 2 * m + 1);
            W[m][0]=wa.x; W[m][1]=wa.y; W[m][2]=wa.z; W[m][3]=wa.w;
            W[m][4]=wb.x; W[m][5]=wb.y; W[m][6]=wb.z; W[m][7]=wb.w;
        }
    }

    float a[8][8];
#pragma unroll
    for (int k = 0; k < 8; k++) {
#pragma unroll
        for (int n = 0; n < 8; n++) {
            float s = 0.0f;
#pragma unroll
            for (int m = 0; m < 8; m++) s = fmaf(W[m][k], C[m][n], s);
            a[k][n] = s * p[k];
        }
    }

    // A in [n][f4] layout, f = hi*8 + k, via float4 stores
#pragma unroll
    for (int n = 0; n < 8; n++) {
        float4 lo = make_float4(a[0][n], a[1][n], a[2][n], a[3][n]);
        float4 hi4 = make_float4(a[4][n], a[5][n], a[6][n], a[7][n]);
        g_A[n * F4 + hi * 2]     = lo;
        g_A[n * F4 + hi * 2 + 1] = hi4;
    }

#pragma unroll
    for (int n = 0; n < 8; n++) {
        float s = 0.0f;
#pragma unroll
        for (int k = 0; k < 8; k++) s += a[k][n];
        g_Asum[n * HI + hi] = s;
    }

    float q[15];
#pragma unroll
    for (int pp = 0; pp < 15; pp++) q[pp] = 0.0f;
#pragma unroll
    for (int k = 0; k < 8; k++)
#pragma unroll
        for (int n1 = 0; n1 < 8; n1++)
#pragma unroll
            for (int n2 = 0; n2 < 8; n2++)
                q[n1 + n2] = fmaf(a[k][n1], a[k][n2], q[n1 + n2]);
#pragma unroll
    for (int pp = 0; pp < 15; pp++) g_Q[pp * HI + hi] = q[pp];
}

// ============================================================
// Pass 0b: fold head axis + scale powers into per-i coefficients.
//   B1[n,i] = sum_h Asum[n,h,i] * sc[h,i]^n
//   B2[p,i] = sum_h Q[p,h,i]    * sc[h,i]^p
// grid = 4 blocks x 256 threads (one thread per i).
// ============================================================
__global__ __launch_bounds__(256) void fold_kernel(
    const float* __restrict__ scale)  // [H, I]
{
    int i = blockIdx.x * 256 + threadIdx.x;  // 0..1023
    float b1[8], b2[15];
#pragma unroll
    for (int n = 0; n < 8; n++) b1[n] = 0.0f;
#pragma unroll
    for (int pp = 0; pp < 15; pp++) b2[pp] = 0.0f;

    for (int h = 0; h < NH; h++) {
        int hi = h * ISZ + i;
        float sc = __ldg(&scale[hi]);
        float pw[15];
        pw[0] = 1.0f;
#pragma unroll
        for (int t = 1; t < 15; t++) pw[t] = pw[t - 1] * sc;
#pragma unroll
        for (int n = 0; n < 8; n++)
            b1[n] = fmaf(g_Asum[n * HI + hi], pw[n], b1[n]);
#pragma unroll
        for (int pp = 0; pp < 15; pp++)
            b2[pp] = fmaf(g_Q[pp * HI + hi], pw[pp], b2[pp]);
    }
#pragma unroll
    for (int n = 0; n < 8; n++)  g_B1[n * ISZ + i]  = b1[n];
#pragma unroll
    for (int pp = 0; pp < 15; pp++) g_B2[pp * ISZ + i] = b2[pp];
}

// ============================================================
// Pass 1: per-row sum/sumsq over i only (head axis pre-folded).
// grid = (4 i-blocks, 32 b-chunks), 256 threads; thread owns one i,
// 8-b register tiles; one smem block-reduction per tile.
// ============================================================
__global__ __launch_bounds__(256) void stats_kernel(
    const float* __restrict__ x)      // [B, I]
{
    __shared__ float red[16 * 256];

    int i = blockIdx.x * 256 + threadIdx.x;  // 0..1023

    float b1[8];
#pragma unroll
    for (int n = 0; n < 8; n++) b1[n] = g_B1[n * ISZ + i];
    float b2[15];
#pragma unroll
    for (int pp = 0; pp < 15; pp++) b2[pp] = g_B2[pp * ISZ + i];

    int b0   = blockIdx.y * 32;
    int w    = threadIdx.x >> 5;
    int lane = threadIdx.x & 31;

    for (int tile = 0; tile < 4; tile++) {
        int bt = b0 + tile * 8;
#pragma unroll
        for (int bb = 0; bb < 8; bb++) {
            float xv = __ldg(&x[(bt + bb) * ISZ + i]);

            float s1 = b1[7];
#pragma unroll
            for (int n = 6; n >= 0; n--) s1 = fmaf(s1, xv, b1[n]);
            float s2 = b2[14];
#pragma unroll
            for (int pp = 13; pp >= 0; pp--) s2 = fmaf(s2, xv, b2[pp]);

            red[(2 * bb)     * 256 + threadIdx.x] = s1;
            red[(2 * bb + 1) * 256 + threadIdx.x] = s2;
        }
        __syncthreads();
#pragma unroll
        for (int s = w; s < 16; s += 8) {
            float v = 0.0f;
#pragma unroll
            for (int j = 0; j < 8; j++) v += red[s * 256 + lane + j * 32];
#pragma unroll
            for (int off = 16; off > 0; off >>= 1)
                v += __shfl_xor_sync(0xFFFFFFFFu, v, off);
            if (lane == 0)
                atomicAdd(&g_S[(s & 1) * BATCH + bt + (s >> 1)], v);
        }
        __syncthreads();
    }
}

// ============================================================
// Pass 1b: mu / rstd per row.
// ============================================================
__global__ void finalize_kernel()
{
    int b = blockIdx.x * blockDim.x + threadIdx.x;
    if (b >= BATCH) return;
    const float inv = 1.0f / (float)FEAT;
    float mu  = g_S[b] * inv;
    float var = g_S[BATCH + b] * inv - mu * mu;
    g_mu[b]   = mu;
    g_rstd[b] = rsqrtf(var + 1e-5f);
}

// ============================================================
// Pass 2: recompute y via Horner, normalize, stream-write output.
// 16-row b tiles (8KB smem) -> 4096 blocks -> ~7 waves (small tail).
// grid = (64 f-blocks, 64 b-chunks), 256 threads.
// ============================================================
__global__ __launch_bounds__(256) void emit_kernel(
    const float* __restrict__ x,
    const float* __restrict__ scale,
    const float* __restrict__ gamma,
    const float* __restrict__ beta,
    float* __restrict__ out)
{
    __shared__ float xs[16 * 128];
    __shared__ float smu[16];
    __shared__ float srs[16];

    int f4 = blockIdx.x * 256 + threadIdx.x;   // 0..16383
    int hi = f4 >> 1;
    int i0 = (blockIdx.x * 128) & (ISZ - 1);   // tile's base i
    int b0 = blockIdx.y * 16;

    // Cooperative stage of x tile: 16 rows x 128 floats = 512 float4
    {
        float4* xs4 = reinterpret_cast<float4*>(xs);
#pragma unroll
        for (int t = threadIdx.x; t < 512; t += 256) {
            int bb = t >> 5;
            int c4 = t & 31;
            xs4[t] = __ldg(reinterpret_cast<const float4*>(
                               x + (b0 + bb) * ISZ + i0) + c4);
        }
    }
    if (threadIdx.x < 16)       smu[threadIdx.x]      = g_mu[b0 + threadIdx.x];
    else if (threadIdx.x < 32)  srs[threadIdx.x - 16] = g_rstd[b0 + threadIdx.x - 16];

    float4 c[8];
#pragma unroll
    for (int n = 0; n < 8; n++) c[n] = g_A[n * F4 + f4];

    float  sc = scale[hi];
    float4 g  = reinterpret_cast<const float4*>(gamma)[f4];
    float4 be = reinterpret_cast<const float4*>(beta)[f4];

    __syncthreads();

    int il = threadIdx.x >> 1;                 // local i within tile
    float4* out4 = reinterpret_cast<float4*>(out);

#pragma unroll 4
    for (int bb = 0; bb < 16; bb++) {
        float xv = xs[bb * 128 + il] * sc;
        float mu = smu[bb];
        float rs = srs[bb];

        float y0 = c[7].x, y1 = c[7].y, y2 = c[7].z, y3 = c[7].w;
#pragma unroll
        for (int n = 6; n >= 0; n--) {
            y0 = fmaf(y0, xv, c[n].x);
            y1 = fmaf(y1, xv, c[n].y);
            y2 = fmaf(y2, xv, c[n].z);
            y3 = fmaf(y3, xv, c[n].w);
        }

        float4 o;
        o.x = fmaf((y0 - mu) * rs, g.x, be.x);
        o.y = fmaf((y1 - mu) * rs, g.y, be.y);
        o.z = fmaf((y2 - mu) * rs, g.z, be.z);
        o.w = fmaf((y3 - mu) * rs, g.w, be.w);
        __stcs(&out4[(size_t)(b0 + bb) * F4 + f4], o);
    }
}

// ============================================================
extern "C" void kernel_launch(void* const* d_in, const int* in_sizes, int n_in,
                              void* d_out, int out_size)
{
    const float* x     = (const float*)d_in[0];  // [1024, 1024]
    const float* scale = (const float*)d_in[1];  // [8, 1024]
    const float* poly  = (const float*)d_in[2];  // [8, 1024, 8]
    const float* kern  = (const float*)d_in[3];  // [8, 1024, 8, 8]
    const float* gamma = (const float*)d_in[4];  // [65536]
    const float* beta  = (const float*)d_in[5];  // [65536]
    float* out = (float*)d_out;                  // [1024, 65536]

    prep_kernel<<<32, 256>>>(poly, kern);
    fold_kernel<<<4, 256>>>(scale);
    stats_kernel<<<dim3(4, 32), 256>>>(x);
    finalize_kernel<<<4, 256>>>();
    emit_kernel<<<dim3(64, 64), 256>>>(x, scale, gamma, beta, out);
}

// round 4
// speedup vs baseline: 2.2798x; 1.1342x over previous
#include <cuda_runtime.h>

// Shapes (fixed by the problem)
#define BATCH 1024
#define ISZ   1024
#define NH    8
#define HI    8192      // NH * ISZ
#define FEAT  65536     // HI * 8
#define F4    16384     // FEAT / 4

// -------- device scratch (no allocations allowed) --------
__device__ float4 g_A[8 * F4];       // monomial coeffs, layout [n][f/4], f = hi*8 + k
__device__ float  g_Asum[8 * HI];    // [n][hi]  : coeffs of sum_k y_k (unscaled)
__device__ float  g_Q[15 * HI];      // [p][hi]  : coeffs of sum_k y_k^2 (unscaled)
__device__ float  g_B1[8 * ISZ];     // [n][i]   : head-folded, scale-folded
__device__ float  g_B2[15 * ISZ];    // [p][i]
__device__ float  g_S[2 * BATCH];    // per-row sum / sumsq accumulators

// ============================================================
// Pass 0: fold kernel * poly * Chebyshev-monomial into A, Asum, Q.
// One thread per (h,i). Also zeroes g_S for this replay.
// ============================================================
__global__ __launch_bounds__(256) void prep_kernel(
    const float* __restrict__ poly,   // [H, I, M]
    const float* __restrict__ kern)   // [H, I, M, K]
{
    int hi = blockIdx.x * blockDim.x + threadIdx.x;
    if (hi < 2 * BATCH) g_S[hi] = 0.0f;
    if (hi >= HI) return;

    // Chebyshev T_m monomial coefficients C[m][n]
    const float C[8][8] = {
        {  1,  0,  0,  0,   0,    0,  0,  0},
        {  0,  1,  0,  0,   0,    0,  0,  0},
        { -1,  0,  2,  0,   0,    0,  0,  0},
        {  0, -3,  0,  4,   0,    0,  0,  0},
        {  1,  0, -8,  0,   8,    0,  0,  0},
        {  0,  5,  0,-20,   0,   16,  0,  0},
        { -1,  0, 18,  0, -48,    0, 32,  0},
        {  0, -7,  0, 56,   0, -112,  0, 64}};

    float p[8];
    float W[8][8];
    {
        const float4* p4 = reinterpret_cast<const float4*>(poly + hi * 8);
        float4 pa = __ldg(p4), pb = __ldg(p4 + 1);
        p[0]=pa.x; p[1]=pa.y; p[2]=pa.z; p[3]=pa.w;
        p[4]=pb.x; p[5]=pb.y; p[6]=pb.z; p[7]=pb.w;
        const float4* k4 = reinterpret_cast<const float4*>(kern + hi * 64);
#pragma unroll
        for (int m = 0; m < 8; m++) {
            float4 wa = __ldg(k4 + 2 * m), wb = __ldg(k4 + 2 * m + 1);
            W[m][0]=wa.x; W[m][1]=wa.y; W[m][2]=wa.z; W[m][3]=wa.w;
            W[m][4]=wb.x; W[m][5]=wb.y; W[m][6]=wb.z; W[m][7]=wb.w;
        }
    }

    float a[8][8];
#pragma unroll
    for (int k = 0; k < 8; k++) {
#pragma unroll
        for (int n = 0; n < 8; n++) {
            float s = 0.0f;
#pragma unroll
            for (int m = 0; m < 8; m++) s = fmaf(W[m][k], C[m][n], s);
            a[k][n] = s * p[k];
        }
    }

    // A in [n][f4] layout, f = hi*8 + k, via float4 stores
#pragma unroll
    for (int n = 0; n < 8; n++) {
        float4 lo  = make_float4(a[0][n], a[1][n], a[2][n], a[3][n]);
        float4 hi4 = make_float4(a[4][n], a[5][n], a[6][n], a[7][n]);
        g_A[n * F4 + hi * 2]     = lo;
        g_A[n * F4 + hi * 2 + 1] = hi4;
    }

#pragma unroll
    for (int n = 0; n < 8; n++) {
        float s = 0.0f;
#pragma unroll
        for (int k = 0; k < 8; k++) s += a[k][n];
        g_Asum[n * HI + hi] = s;
    }

    float q[15];
#pragma unroll
    for (int pp = 0; pp < 15; pp++) q[pp] = 0.0f;
#pragma unroll
    for (int k = 0; k < 8; k++)
#pragma unroll
        for (int n1 = 0; n1 < 8; n1++)
#pragma unroll
            for (int n2 = 0; n2 < 8; n2++)
                q[n1 + n2] = fmaf(a[k][n1], a[k][n2], q[n1 + n2]);
#pragma unroll
    for (int pp = 0; pp < 15; pp++) g_Q[pp * HI + hi] = q[pp];
}

// ============================================================
// Pass 0b: fold head axis + scale powers into per-i coefficients.
// grid = (4, 23): blockIdx.y selects the output coefficient
// (0..7 -> B1 degree n, 8..22 -> B2 degree p). One thread per i.
// ============================================================
__global__ __launch_bounds__(256) void fold_kernel(
    const float* __restrict__ scale)  // [H, I]
{
    int i = blockIdx.x * 256 + threadIdx.x;  // 0..1023
    int c = blockIdx.y;                      // 0..22
    int deg = (c < 8) ? c : (c - 8);

    float acc = 0.0f;
#pragma unroll
    for (int h = 0; h < NH; h++) {
        int hi = h * ISZ + i;
        float sc = __ldg(&scale[hi]);
        float pw = 1.0f;
        for (int t = 0; t < deg; t++) pw *= sc;
        float coef = (c < 8) ? g_Asum[c * HI + hi] : g_Q[(c - 8) * HI + hi];
        acc = fmaf(coef, pw, acc);
    }
    if (c < 8) g_B1[c * ISZ + i]       = acc;
    else       g_B2[(c - 8) * ISZ + i] = acc;
}

// ============================================================
// Pass 1: per-row sum/sumsq over i only (head axis pre-folded).
// grid = (4 i-blocks, 32 b-chunks), 256 threads.
// ============================================================
__global__ __launch_bounds__(256) void stats_kernel(
    const float* __restrict__ x)      // [B, I]
{
    __shared__ float red[16 * 256];

    int i = blockIdx.x * 256 + threadIdx.x;  // 0..1023

    float b1[8];
#pragma unroll
    for (int n = 0; n < 8; n++) b1[n] = g_B1[n * ISZ + i];
    float b2[15];
#pragma unroll
    for (int pp = 0; pp < 15; pp++) b2[pp] = g_B2[pp * ISZ + i];

    int b0   = blockIdx.y * 32;
    int w    = threadIdx.x >> 5;
    int lane = threadIdx.x & 31;

    for (int tile = 0; tile < 4; tile++) {
        int bt = b0 + tile * 8;
#pragma unroll
        for (int bb = 0; bb < 8; bb++) {
            float xv = __ldg(&x[(bt + bb) * ISZ + i]);

            float s1 = b1[7];
#pragma unroll
            for (int n = 6; n >= 0; n--) s1 = fmaf(s1, xv, b1[n]);
            float s2 = b2[14];
#pragma unroll
            for (int pp = 13; pp >= 0; pp--) s2 = fmaf(s2, xv, b2[pp]);

            red[(2 * bb)     * 256 + threadIdx.x] = s1;
            red[(2 * bb + 1) * 256 + threadIdx.x] = s2;
        }
        __syncthreads();
#pragma unroll
        for (int s = w; s < 16; s += 8) {
            float v = 0.0f;
#pragma unroll
            for (int j = 0; j < 8; j++) v += red[s * 256 + lane + j * 32];
#pragma unroll
            for (int off = 16; off > 0; off >>= 1)
                v += __shfl_xor_sync(0xFFFFFFFFu, v, off);
            if (lane == 0)
                atomicAdd(&g_S[(s & 1) * BATCH + bt + (s >> 1)], v);
        }
        __syncthreads();
    }
}

// ============================================================
// Pass 2: recompute y via Horner (gamma folded into coefficients),
// normalize, stream-write output. mu/rstd computed inline from g_S.
// grid = (64 f-blocks, 64 b-chunks), 256 threads, 16-row b tiles.
// ============================================================
__global__ __launch_bounds__(256) void emit_kernel(
    const float* __restrict__ x,
    const float* __restrict__ scale,
    const float* __restrict__ gamma,
    const float* __restrict__ beta,
    float* __restrict__ out)
{
    __shared__ float xs[16 * 128];
    __shared__ float smu[16];
    __shared__ float srs[16];

    int f4 = blockIdx.x * 256 + threadIdx.x;   // 0..16383
    int hi = f4 >> 1;
    int i0 = (blockIdx.x * 128) & (ISZ - 1);   // tile's base i
    int b0 = blockIdx.y * 16;

    // Cooperative stage of x tile: 16 rows x 128 floats = 512 float4
    {
        float4* xs4 = reinterpret_cast<float4*>(xs);
#pragma unroll
        for (int t = threadIdx.x; t < 512; t += 256) {
            int bb = t >> 5;
            int c4 = t & 31;
            xs4[t] = __ldg(reinterpret_cast<const float4*>(
                               x + (b0 + bb) * ISZ + i0) + c4);
        }
    }
    // Inline finalize: mu/rstd for this block's 16 rows
    if (threadIdx.x < 16) {
        const float inv = 1.0f / (float)FEAT;
        int b = b0 + threadIdx.x;
        float mu  = g_S[b] * inv;
        float var = g_S[BATCH + b] * inv - mu * mu;
        smu[threadIdx.x] = mu;
        srs[threadIdx.x] = rsqrtf(var + 1e-5f);
    }

    float4 g  = reinterpret_cast<const float4*>(gamma)[f4];
    float4 be = reinterpret_cast<const float4*>(beta)[f4];
    float  sc = scale[hi];

    // Fold gamma into Horner coefficients (linear): c' = c * g
    float4 c[8];
#pragma unroll
    for (int n = 0; n < 8; n++) {
        float4 cn = g_A[n * F4 + f4];
        cn.x *= g.x; cn.y *= g.y; cn.z *= g.z; cn.w *= g.w;
        c[n] = cn;
    }

    __syncthreads();

    int il = threadIdx.x >> 1;                 // local i within tile
    float4* out4 = reinterpret_cast<float4*>(out);

#pragma unroll 4
    for (int bb = 0; bb < 16; bb++) {
        float xv = xs[bb * 128 + il] * sc;
        float rs = srs[bb];
        float t  = smu[bb] * rs;               // mu * rstd (scalar)

        float y0 = c[7].x, y1 = c[7].y, y2 = c[7].z, y3 = c[7].w;
#pragma unroll
        for (int n = 6; n >= 0; n--) {
            y0 = fmaf(y0, xv, c[n].x);
            y1 = fmaf(y1, xv, c[n].y);
            y2 = fmaf(y2, xv, c[n].z);
            y3 = fmaf(y3, xv, c[n].w);
        }

        // o = (H*g)*rs + (be - mu*rs*g)
        float4 o;
        o.x = fmaf(y0, rs, fmaf(-t, g.x, be.x));
        o.y = fmaf(y1, rs, fmaf(-t, g.y, be.y));
        o.z = fmaf(y2, rs, fmaf(-t, g.z, be.z));
        o.w = fmaf(y3, rs, fmaf(-t, g.w, be.w));
        __stcs(&out4[(size_t)(b0 + bb) * F4 + f4], o);
    }
}

// ============================================================
extern "C" void kernel_launch(void* const* d_in, const int* in_sizes, int n_in,
                              void* d_out, int out_size)
{
    const float* x     = (const float*)d_in[0];  // [1024, 1024]
    const float* scale = (const float*)d_in[1];  // [8, 1024]
    const float* poly  = (const float*)d_in[2];  // [8, 1024, 8]
    const float* kern  = (const float*)d_in[3];  // [8, 1024, 8, 8]
    const float* gamma = (const float*)d_in[4];  // [65536]
    const float* beta  = (const float*)d_in[5];  // [65536]
    float* out = (float*)d_out;                  // [1024, 65536]

    prep_kernel<<<32, 256>>>(poly, kern);
    fold_kernel<<<dim3(4, 23), 256>>>(scale);
    stats_kernel<<<dim3(4, 32), 256>>>(x);
    emit_kernel<<<dim3(64, 64), 256>>>(x, scale, gamma, beta, out);
}